// round 6
// baseline (speedup 1.0000x reference)
#include <cuda_runtime.h>
#include <cstdint>
#include <cstddef>

// ============================================================
// Problem dims (fixed)
// ============================================================
#define MROWS 8192
#define NDIM  4096
#define KDIM  4096
#define KGROUPS 32                   // 4096 / 128 quant groups per row

// GEMM tiling: CTA 128x128, 8 warps (2 M x 4 N), warp tile 64x32
#define TM 128
#define TN 128
#define KB 128                       // K int8 per stage = ONE quant group
#define NKB (KDIM / KB)              // 32
#define NSTAGES 5
#define A_BYTES (TM * 128)           // 16384
#define B_BYTES (TN * 128)           // 16384
#define STAGE_BYTES (A_BYTES + B_BYTES)            // 32768
#define SW_BYTES (KGROUPS * TN * 4)                // 16384 group scales in SMEM
#define GEMM_SMEM (SW_BYTES + NSTAGES * STAGE_BYTES)   // 180224

#define THREADS 256

// int bit pattern of 12582912.0f (2^23 + 2^22): magic bias for exact int->float
#define MAGIC_I 0x4B400000
#define MAGIC_F 12582912.0f

// ============================================================
// Scratch (static __device__ — no runtime allocation)
// ============================================================
__device__ signed char g_XQ[(size_t)MROWS * KDIM];   // 32 MB: qx int8 (exact)
__device__ signed char g_WQ[(size_t)NDIM * KDIM];    // 16 MB: wq = (q - z) in [0,15]
__device__ float g_SX[MROWS];                        // activation scale per row
__device__ float g_ZX[MROWS];                        // activation zero per row
__device__ float g_WS[(size_t)NDIM * KGROUPS];       // weight group scale sw[n][g]
__device__ float g_WGS[(size_t)NDIM * KGROUPS];      // sw[n][g] * sum_{k in g} wq
__device__ float g_WSUM[NDIM];                       // sum_k w_deq[n][k]

// ============================================================
// PTX helpers (sm_100 baseline ISA — no 'a'-suffix features)
// ============================================================
__device__ __forceinline__ uint32_t smem_u32(const void* p) {
    uint32_t a;
    asm("{ .reg .u64 t; cvta.to.shared.u64 t, %1; cvt.u32.u64 %0, t; }" : "=r"(a) : "l"(p));
    return a;
}

#define CP16(smem_addr, gptr) \
    asm volatile("cp.async.cg.shared.global [%0], [%1], 16;" :: "r"(smem_addr), "l"(gptr) : "memory")
#define CP_COMMIT()  asm volatile("cp.async.commit_group;" ::: "memory")
#define CP_WAIT3()   asm volatile("cp.async.wait_group 3;" ::: "memory")
#define CP_WAIT0()   asm volatile("cp.async.wait_group 0;" ::: "memory")

#define LDSM_X4(r0, r1, r2, r3, addr)                                        \
    asm volatile("ldmatrix.sync.aligned.m8n8.x4.shared.b16 {%0,%1,%2,%3}, [%4];" \
                 : "=r"(r0), "=r"(r1), "=r"(r2), "=r"(r3) : "r"(addr))

#define MMAS8(c, a, b0, b1)                                                  \
    asm volatile("mma.sync.aligned.m16n8k32.row.col.s32.s8.s8.s32 "          \
                 "{%0,%1,%2,%3}, {%4,%5,%6,%7}, {%8,%9}, {%0,%1,%2,%3};"     \
                 : "+r"((c)[0]), "+r"((c)[1]), "+r"((c)[2]), "+r"((c)[3])    \
                 : "r"((a)[0]), "r"((a)[1]), "r"((a)[2]), "r"((a)[3]),       \
                   "r"((b0)), "r"((b1)))

// Stage load: A rows {r0,+32,+64,+96}, B rows same; one 16B chunk/row/thread.
#define LOAD_STAGE(kb)                                                        \
    do {                                                                      \
        const uint32_t so_ = (uint32_t)((kb) % NSTAGES) * STAGE_BYTES;        \
        const signed char* pA = gA + (size_t)(kb) * 128;                      \
        const signed char* pB = gB + (size_t)(kb) * 128;                      \
        CP16(smA + so_,            pA);                                       \
        CP16(smA + so_ + 32 * 128, pA + (size_t)32 * KDIM);                   \
        CP16(smA + so_ + 64 * 128, pA + (size_t)64 * KDIM);                   \
        CP16(smA + so_ + 96 * 128, pA + (size_t)96 * KDIM);                   \
        CP16(smB + so_,            pB);                                       \
        CP16(smB + so_ + 32 * 128, pB + (size_t)32 * KDIM);                   \
        CP16(smB + so_ + 64 * 128, pB + (size_t)64 * KDIM);                   \
        CP16(smB + so_ + 96 * 128, pB + (size_t)96 * KDIM);                   \
        CP_COMMIT();                                                          \
    } while (0)

// ============================================================
// Kernel 1: weight group quant (gs=128, nbit=4, asym) -> int8 wq + scales
// scale=(max-min)/15, z=-8-rint(min/s), q=clip(rint(w/s)+z,-8,7), wq=q-z
// ============================================================
__global__ void __launch_bounds__(256) w_quant_kernel(const float* __restrict__ w) {
    int g    = blockIdx.x * 8 + (threadIdx.x >> 5);   // group id = n*32 + gk
    int lane = threadIdx.x & 31;
    const float4 f = ((const float4*)(w + (size_t)g * 128))[lane];

    float v[4] = {f.x, f.y, f.z, f.w};
    float mn = fminf(fminf(v[0], v[1]), fminf(v[2], v[3]));
    float mx = fmaxf(fmaxf(v[0], v[1]), fmaxf(v[2], v[3]));
#pragma unroll
    for (int off = 16; off > 0; off >>= 1) {
        mn = fminf(mn, __shfl_xor_sync(0xffffffffu, mn, off));
        mx = fmaxf(mx, __shfl_xor_sync(0xffffffffu, mx, off));
    }
    float sc = __fdiv_rn(mx - mn, 15.0f);
    if (!(sc > 0.0f)) sc = 1.0f;
    float z = -8.0f - rintf(__fdiv_rn(mn, sc));

    float gsum = 0.0f;
    signed char o[4];
#pragma unroll
    for (int j = 0; j < 4; j++) {
        float q = rintf(__fdiv_rn(v[j], sc)) + z;
        q = fminf(fmaxf(q, -8.0f), 7.0f);
        float wq = q - z;                 // exact small integer in [0,15]
        gsum += wq;
        o[j] = (signed char)__float2int_rn(wq);
    }
    ((char4*)(g_WQ + (size_t)g * 128))[lane] = make_char4(o[0], o[1], o[2], o[3]);
#pragma unroll
    for (int off = 16; off > 0; off >>= 1)
        gsum += __shfl_xor_sync(0xffffffffu, gsum, off);
    if (lane == 0) {
        g_WS[g]  = sc;
        g_WGS[g] = sc * gsum;
    }
}

// ============================================================
// Kernel 1b: WSUM[n] = sum_g g_WGS[n*32+g]  (one warp per n-row)
// ============================================================
__global__ void __launch_bounds__(256) wsum_kernel() {
    int n    = blockIdx.x * 8 + (threadIdx.x >> 5);
    int lane = threadIdx.x & 31;
    float v = g_WGS[(size_t)n * KGROUPS + lane];
#pragma unroll
    for (int off = 16; off > 0; off >>= 1)
        v += __shfl_xor_sync(0xffffffffu, v, off);
    if (lane == 0) g_WSUM[n] = v;
}

// ============================================================
// Kernel 2: activation dynamic per-row int8 quant -> qx int8, sx, zx
// ============================================================
__global__ void __launch_bounds__(256) act_quant_kernel(const float* __restrict__ x) {
    int row = blockIdx.x;
    int tid = threadIdx.x;
    const float4* xr4 = (const float4*)(x + (size_t)row * KDIM);

    float vals[16];
    float mn = 3.4e38f, mx = -3.4e38f;
#pragma unroll
    for (int j = 0; j < 4; j++) {
        float4 f = xr4[tid + j * 256];
        vals[4 * j + 0] = f.x; vals[4 * j + 1] = f.y;
        vals[4 * j + 2] = f.z; vals[4 * j + 3] = f.w;
        mn = fminf(mn, fminf(fminf(f.x, f.y), fminf(f.z, f.w)));
        mx = fmaxf(mx, fmaxf(fmaxf(f.x, f.y), fmaxf(f.z, f.w)));
    }
#pragma unroll
    for (int off = 16; off > 0; off >>= 1) {
        mn = fminf(mn, __shfl_xor_sync(0xffffffffu, mn, off));
        mx = fmaxf(mx, __shfl_xor_sync(0xffffffffu, mx, off));
    }
    __shared__ float smin[8], smax[8];
    __shared__ float s_sc, s_z;
    if ((tid & 31) == 0) { smin[tid >> 5] = mn; smax[tid >> 5] = mx; }
    __syncthreads();
    if (tid == 0) {
        float rmn = smin[0], rmx = smax[0];
#pragma unroll
        for (int i = 1; i < 8; i++) { rmn = fminf(rmn, smin[i]); rmx = fmaxf(rmx, smax[i]); }
        float sc = __fdiv_rn(rmx - rmn, 255.0f);
        if (!(sc > 0.0f)) sc = 1.0f;
        float z = -128.0f - rintf(__fdiv_rn(rmn, sc));
        s_sc = sc; s_z = z;
        g_SX[row] = sc;
        g_ZX[row] = z;
    }
    __syncthreads();
    float sc = s_sc, z = s_z;
    char4* outp4 = (char4*)(g_XQ + (size_t)row * KDIM);
#pragma unroll
    for (int j = 0; j < 4; j++) {
        signed char o[4];
#pragma unroll
        for (int e = 0; e < 4; e++) {
            float q = rintf(__fdiv_rn(vals[4 * j + e], sc)) + z;
            q = fminf(fmaxf(q, -128.0f), 127.0f);
            o[e] = (signed char)__float2int_rn(q);
        }
        outp4[tid + j * 256] = make_char4(o[0], o[1], o[2], o[3]);
    }
}

// ============================================================
// Kernel 3: int8 IMMA GEMM, per-group scale fold via magic-bias (no I2F)
//   ic initialized to MAGIC_I; after group MMAs, float bits of ic are
//   exactly 12582912 + S1 -> FSUB recovers S1 exactly, FFMA folds sw.
// CTA 128x128, 8 warps (2x4), warp tile 64x32; 5-stage cp.async pipeline,
// single __syncthreads per stage, uniform commit (empty group in tail).
// ============================================================
__global__ void __launch_bounds__(THREADS, 1)
gemm_kernel(float* __restrict__ out) {
    extern __shared__ char smem[];
    const uint32_t swbase = smem_u32(smem);          // [32 g][128 n] fp32 = 16 KB
    const uint32_t tiles  = swbase + SW_BYTES;

    const int tid  = threadIdx.x;
    const int wid  = tid >> 5;
    const int lane = tid & 31;
    const int wm   = wid & 1;        // 0..1  (M)
    const int wn   = wid >> 1;       // 0..3  (N)

    const int m0 = blockIdx.y * TM;
    const int n0 = blockIdx.x * TN;

    // ---------- producer addressing ----------
    const int  r0  = tid >> 3;       // 0..31
    const int  c   = tid & 7;        // 16B chunk within 128B row
    const uint32_t swz = (uint32_t)(((c ^ (r0 & 7)) & 7) * 16);

    const signed char* gA = g_XQ + (size_t)(m0 + r0) * KDIM + c * 16;
    const signed char* gB = g_WQ + (size_t)(n0 + r0) * KDIM + c * 16;
    const uint32_t smA = tiles + (uint32_t)r0 * 128 + swz;
    const uint32_t smB = tiles + A_BYTES + (uint32_t)r0 * 128 + swz;

    // ---------- stage the group scales: sw_s[g][n] ----------
    for (int idx = tid; idx < KGROUPS * TN; idx += THREADS) {
        int n = idx >> 5;
        int g = idx & 31;
        ((float*)smem)[g * TN + n] = g_WS[(size_t)(n0 + n) * KGROUPS + g];
    }

    // ---------- consumer (ldmatrix) addressing ----------
    const uint32_t xr = (uint32_t)((lane & 7) * 16);
    const uint32_t adA0 = tiles +
        (uint32_t)(wm * 64 + (lane & 7) + ((lane >> 3) & 1) * 8) * 128;
    const uint32_t ach = (uint32_t)((lane >> 4) * 16);
    const uint32_t adB0 = tiles + A_BYTES +
        (uint32_t)(wn * 32 + (lane & 7) + (lane >> 4) * 8) * 128;
    const uint32_t bch = (uint32_t)(((lane >> 3) & 1) * 16);

    float facc[4][4][4];
#pragma unroll
    for (int i = 0; i < 4; i++)
#pragma unroll
        for (int j = 0; j < 4; j++)
#pragma unroll
            for (int q = 0; q < 4; q++) facc[i][j][q] = 0.0f;

    const int ncol2 = (lane & 3) * 2;

    // ---------- prologue: 4 stages in flight ----------
    LOAD_STAGE(0);
    LOAD_STAGE(1);
    LOAD_STAGE(2);
    LOAD_STAGE(3);

    // ---------- main loop: one quant group per iteration ----------
    for (int kb = 0; kb < NKB; kb++) {
        // Commits before this wait: 4 + kb. wait<=3 pending => commit #kb
        // (== stage kb) is complete. Tail issues empty groups so the count
        // stays uniform.
        CP_WAIT3();
        __syncthreads();

        const uint32_t so = (uint32_t)(kb % NSTAGES) * STAGE_BYTES;

        // group scales for this thread's 8 n-columns
        float swr[8];
        {
            const float* swp = (const float*)smem + (size_t)kb * TN + wn * 32 + ncol2;
#pragma unroll
            for (int nf = 0; nf < 4; nf++) {
                float2 s2 = *(const float2*)(swp + nf * 8);
                swr[2 * nf]     = s2.x;
                swr[2 * nf + 1] = s2.y;
            }
        }

        // B fragments for all 4 k-steps
        uint32_t bu[4][8];
#pragma unroll
        for (int ks = 0; ks < 4; ks++) {
            const uint32_t kc = (uint32_t)(ks * 32);
            LDSM_X4(bu[ks][0], bu[ks][1], bu[ks][2], bu[ks][3],
                    adB0 + so + ((kc + bch) ^ xr));
            LDSM_X4(bu[ks][4], bu[ks][5], bu[ks][6], bu[ks][7],
                    adB0 + 2048 + so + ((kc + bch) ^ xr));
        }

        // A fragment double-buffer: prefetch (mf,ks)+1 while MMAs run
        uint32_t ab[2][4];
        LDSM_X4(ab[0][0], ab[0][1], ab[0][2], ab[0][3],
                adA0 + so + (ach ^ xr));

        // issue next stage's global loads (or empty commit in tail)
        if (kb + 4 < NKB) { LOAD_STAGE(kb + 4); } else { CP_COMMIT(); }

#pragma unroll
        for (int mf = 0; mf < 4; mf++) {
            int ic[4][4];
#pragma unroll
            for (int nf = 0; nf < 4; nf++)
#pragma unroll
                for (int q = 0; q < 4; q++) ic[nf][q] = MAGIC_I;

#pragma unroll
            for (int ks = 0; ks < 4; ks++) {
                const int idx = mf * 4 + ks;
                const int cur = idx & 1;
                if (idx < 15) {
                    const int nmf = (ks == 3) ? mf + 1 : mf;
                    const int nks = (ks == 3) ? 0 : ks + 1;
                    LDSM_X4(ab[cur ^ 1][0], ab[cur ^ 1][1], ab[cur ^ 1][2], ab[cur ^ 1][3],
                            adA0 + (uint32_t)nmf * 2048 + so +
                            (((uint32_t)(nks * 32) + ach) ^ xr));
                }
#pragma unroll
                for (int nf = 0; nf < 4; nf++)
                    MMAS8(ic[nf], ab[cur], bu[ks][2 * nf], bu[ks][2 * nf + 1]);
            }
            // fold group: S1 = float_bits(ic) - MAGIC (exact); facc += S1*sw
#pragma unroll
            for (int nf = 0; nf < 4; nf++) {
                facc[mf][nf][0] = __fmaf_rn(__fsub_rn(__int_as_float(ic[nf][0]), MAGIC_F),
                                            swr[2 * nf],     facc[mf][nf][0]);
                facc[mf][nf][1] = __fmaf_rn(__fsub_rn(__int_as_float(ic[nf][1]), MAGIC_F),
                                            swr[2 * nf + 1], facc[mf][nf][1]);
                facc[mf][nf][2] = __fmaf_rn(__fsub_rn(__int_as_float(ic[nf][2]), MAGIC_F),
                                            swr[2 * nf],     facc[mf][nf][2]);
                facc[mf][nf][3] = __fmaf_rn(__fsub_rn(__int_as_float(ic[nf][3]), MAGIC_F),
                                            swr[2 * nf + 1], facc[mf][nf][3]);
            }
        }
    }
    CP_WAIT0();

    // ---------- epilogue: y = sx*(facc - zx*WSUM[n]) ----------
#pragma unroll
    for (int mf = 0; mf < 4; mf++) {
        const int m_lo = m0 + wm * 64 + mf * 16 + (lane >> 2);
        const int m_hi = m_lo + 8;
        const float sx0 = g_SX[m_lo], zx0 = g_ZX[m_lo];
        const float sx1 = g_SX[m_hi], zx1 = g_ZX[m_hi];
        float* row_lo = out + (size_t)m_lo * NDIM + n0 + wn * 32 + ncol2;
        float* row_hi = out + (size_t)m_hi * NDIM + n0 + wn * 32 + ncol2;
#pragma unroll
        for (int nf = 0; nf < 4; nf++) {
            const int ng = n0 + wn * 32 + nf * 8 + ncol2;
            const float ws0 = g_WSUM[ng];
            const float ws1 = g_WSUM[ng + 1];
            float2 v0, v1;
            v0.x = sx0 * (facc[mf][nf][0] - zx0 * ws0);
            v0.y = sx0 * (facc[mf][nf][1] - zx0 * ws1);
            v1.x = sx1 * (facc[mf][nf][2] - zx1 * ws0);
            v1.y = sx1 * (facc[mf][nf][3] - zx1 * ws1);
            *(float2*)(row_lo + nf * 8) = v0;
            *(float2*)(row_hi + nf * 8) = v1;
        }
    }
}

// ============================================================
// Launcher
// ============================================================
extern "C" void kernel_launch(void* const* d_in, const int* in_sizes, int n_in,
                              void* d_out, int out_size) {
    const float* x = (const float*)d_in[0];   // [4, 2048, 4096] fp32
    const float* w = (const float*)d_in[1];   // [4096, 4096] fp32
    float* out = (float*)d_out;               // [4, 2048, 4096] fp32

    cudaFuncSetAttribute(gemm_kernel, cudaFuncAttributeMaxDynamicSharedMemorySize, GEMM_SMEM);

    w_quant_kernel<<<16384, 256>>>(w);        // 131072 groups / 8 per block
    wsum_kernel<<<512, 256>>>();              // 4096 rows / 8 per block
    act_quant_kernel<<<MROWS, 256>>>(x);
    gemm_kernel<<<dim3(NDIM / TN, MROWS / TM), THREADS, GEMM_SMEM>>>(out);
}